// round 13
// baseline (speedup 1.0000x reference)
#include <cuda_runtime.h>
#include <cuda_fp16.h>
#include <math.h>
#include <stdint.h>

// ---------------------------------------------------------------------------
// VisitTransformer on GB300 — compact rows, fp16 mma.sync GEMMs (64-wide
// K-stages) + fp16 ldmatrix attention; LN fused into Wo/W2 epilogues; output
// expansion fused into the final W2 epilogue.
// Compact: 129 rows/person (128 real + 1 pad row; pad key multiplicity 382).
// ---------------------------------------------------------------------------

#define B_    128
#define V_    128
#define CPV   16
#define SEQ   510
#define PADV  382
#define D_    256
#define DH    128
#define DFF   1024
#define R_    129
#define MROWS (B_ * R_)    // 16512
#define NL    2

// scratch (device globals; allocation-free rule)
__device__ float  g_x   [MROWS * D_];
__device__ __align__(16) __half g_qkvh[MROWS * 768];
__device__ __align__(16) __half g_xh  [MROWS * D_];
__device__ __align__(16) __half g_ctxh[MROWS * D_];
__device__ __align__(16) __half g_h1h [MROWS * DFF];
__device__ __align__(16) __half g_wqkvh[NL * 768 * 256];   // [n][k]
__device__ __align__(16) __half g_woh  [NL * 256 * 256];   // [n][k]
__device__ __align__(16) __half g_w1h  [NL * 1024 * 256];  // [n][k]
__device__ __align__(16) __half g_w2h  [NL * 256 * 1024];  // [n][k]
__device__ float  g_bqkv[NL * 768];

// ---------------------------------------------------------------------------
// helpers
// ---------------------------------------------------------------------------
__device__ __forceinline__ uint32_t smem_u32(const void* p) {
    uint32_t r;
    asm("{ .reg .u64 t; cvta.to.shared.u64 t, %1; cvt.u32.u64 %0, t; }"
        : "=r"(r) : "l"(p));
    return r;
}
#define CP16(dst, src) \
    asm volatile("cp.async.cg.shared.global [%0], [%1], 16;" \
                 :: "r"(dst), "l"(src) : "memory")
#define CP_COMMIT() asm volatile("cp.async.commit_group;" ::: "memory")
#define CP_WAIT1()  asm volatile("cp.async.wait_group 1;" ::: "memory")

#define LDSM4(r0, r1, r2, r3, addr) \
    asm volatile("ldmatrix.sync.aligned.m8n8.x4.shared.b16 {%0,%1,%2,%3}, [%4];" \
                 : "=r"(r0), "=r"(r1), "=r"(r2), "=r"(r3) : "r"(addr))
#define LDSM4T(r0, r1, r2, r3, addr) \
    asm volatile("ldmatrix.sync.aligned.m8n8.x4.trans.shared.b16 {%0,%1,%2,%3}, [%4];" \
                 : "=r"(r0), "=r"(r1), "=r"(r2), "=r"(r3) : "r"(addr))

__device__ __forceinline__ void mma_f16(float* c, const uint32_t* a,
                                        uint32_t b0, uint32_t b1) {
    asm volatile(
        "mma.sync.aligned.m16n8k16.row.col.f32.f16.f16.f32 "
        "{%0,%1,%2,%3}, {%4,%5,%6,%7}, {%8,%9}, {%0,%1,%2,%3};"
        : "+f"(c[0]), "+f"(c[1]), "+f"(c[2]), "+f"(c[3])
        : "r"(a[0]), "r"(a[1]), "r"(a[2]), "r"(a[3]), "r"(b0), "r"(b1));
}

// ---------------------------------------------------------------------------
// 1) Embedding + pad rows (merged)
// ---------------------------------------------------------------------------
__global__ __launch_bounds__(256) void embed_kernel(
    const int* __restrict__ codes, const float* __restrict__ times,
    const float* __restrict__ emb, const float* __restrict__ pad_emb)
{
    int d = threadIdx.x;
    if (blockIdx.x >= B_ * V_) {
        int b = blockIdx.x - B_ * V_;
        float r = pad_emb[d];
        size_t off = (size_t)(b * R_ + V_) * D_ + d;
        g_x[off]  = r;
        g_xh[off] = __float2half(r);
        return;
    }
    int t = blockIdx.x;
    int b = t >> 7, vv = t & 127;

    float acc = 0.f;
    const int* cp = codes + t * CPV;
#pragma unroll
    for (int c = 0; c < CPV; c++) {
        int code = __ldg(cp + c);
        acc += __ldg(emb + (size_t)code * D_ + d);
    }
    float tm = fminf(fmaxf(__ldg(times + t), 0.f), 364.f);
    int j = d & 127;
    float ts  = exp2f(-0.051905126482615036f * (float)j);
    float ang = tm * ts;
    float te  = (d < 128) ? sinf(ang) : cosf(ang);
    float r = acc + te;
    size_t off = (size_t)(b * R_ + vv) * D_ + d;
    g_x[off]  = r;
    g_xh[off] = __float2half(r);
}

// ---------------------------------------------------------------------------
// 2) Weight packing: transpose + convert to fp16 [N][K]. grid.z = job.
// ---------------------------------------------------------------------------
__global__ void pack_all_kernel(
    const float* __restrict__ Wq, const float* __restrict__ Wk,
    const float* __restrict__ Wv, const float* __restrict__ Wo,
    const float* __restrict__ W1, const float* __restrict__ W2)
{
    __shared__ float t[32][33];
    int job = blockIdx.z;
    int l = job & 1, w = job >> 1;
    const float* src; __half* dst; int K, N;
    switch (w) {
        case 0:  src = Wq + (size_t)l * 65536;  dst = g_wqkvh + ((size_t)l * 768 + 0)   * 256; K = 256;  N = 256;  break;
        case 1:  src = Wk + (size_t)l * 65536;  dst = g_wqkvh + ((size_t)l * 768 + 256) * 256; K = 256;  N = 256;  break;
        case 2:  src = Wv + (size_t)l * 65536;  dst = g_wqkvh + ((size_t)l * 768 + 512) * 256; K = 256;  N = 256;  break;
        case 3:  src = Wo + (size_t)l * 65536;  dst = g_woh  + (size_t)l * 65536;  K = 256;  N = 256;  break;
        case 4:  src = W1 + (size_t)l * 262144; dst = g_w1h  + (size_t)l * 262144; K = 256;  N = 1024; break;
        default: src = W2 + (size_t)l * 262144; dst = g_w2h  + (size_t)l * 262144; K = 1024; N = 256;  break;
    }
    int n0, k0;
    if (w == 5) { k0 = blockIdx.x * 32; n0 = blockIdx.y * 32; }
    else        { n0 = blockIdx.x * 32; k0 = blockIdx.y * 32; }
    if (n0 >= N || k0 >= K) return;
    int x = threadIdx.x, y = threadIdx.y;
#pragma unroll
    for (int i = 0; i < 32; i += 8)
        t[y + i][x] = src[(size_t)(k0 + y + i) * N + n0 + x];
    __syncthreads();
#pragma unroll
    for (int i = 0; i < 32; i += 8)
        dst[(size_t)(n0 + y + i) * K + k0 + x] = __float2half(t[x][y + i]);
}

__global__ void pack_bqkv_kernel(
    const float* __restrict__ bq, const float* __restrict__ bk,
    const float* __restrict__ bv)
{
    int idx = blockIdx.x * 256 + threadIdx.x;
    int l = idx / 768, n = idx - l * 768;
    int sel = n >> 8, nn = n & 255;
    const float* bb = (sel == 0) ? bq : (sel == 1) ? bk : bv;
    g_bqkv[idx] = bb[l * 256 + nn];
}

// ---------------------------------------------------------------------------
// 3) fp16 mma.sync GEMM (QKV, W1): C[M,N] = A@Bt^T + bias.
//    Block 128x128, 8 warps (4Mx2N), K-stage 64 halves, 3-stage cp.async,
//    row stride 72 halves (9r mod 8 distinct -> LDSM conflict-free).
//    flags: bit0 relu, bit1 fp16 output.
// ---------------------------------------------------------------------------
#define HSTG 36864                        // A 18432 + B 18432 per stage
#define HGEMM_SMEM (3 * HSTG)             // 110592

__global__ __launch_bounds__(256, 2) void hgemm_kernel(
    const __half* __restrict__ A, const __half* __restrict__ Bt,
    const float* __restrict__ bias, void* __restrict__ Cp,
    int M, int N, int K, int flags)
{
    extern __shared__ char smc[];
    uint32_t sb = smem_u32(smc);

    int tid = threadIdx.x;
    int wid = tid >> 5, lane = tid & 31;
    int warp_m = wid & 3;
    int warp_n = wid >> 2;
    int nb = warp_n * 64;
    int row0 = blockIdx.y * 128;
    int col0 = blockIdx.x * 128;
    int lr = lane >> 2, lc = lane & 3;

    float acc[2][8][4];
#pragma unroll
    for (int mt = 0; mt < 2; mt++)
#pragma unroll
        for (int nt = 0; nt < 8; nt++)
#pragma unroll
            for (int i = 0; i < 4; i++) acc[mt][nt][i] = 0.f;

    const int S = K >> 6;                 // 64-wide K stages (K >= 256)

    auto load_stage = [&](int s, int bufi) {
        int k0 = s << 6;
        uint32_t base = sb + bufi * HSTG;
#pragma unroll
        for (int i = 0; i < 4; i++) {
            int e = tid + i * 256;        // 0..1023
            int r = e >> 3, c = e & 7;
            CP16(base + (uint32_t)(r * 72 + c * 8) * 2,
                 A + (size_t)(row0 + r) * K + k0 + c * 8);
        }
#pragma unroll
        for (int i = 0; i < 4; i++) {
            int e = tid + i * 256;
            int r = e >> 3, c = e & 7;
            CP16(base + 18432 + (uint32_t)(r * 72 + c * 8) * 2,
                 Bt + (size_t)(col0 + r) * K + k0 + c * 8);
        }
    };

    load_stage(0, 0); CP_COMMIT();
    load_stage(1, 1); CP_COMMIT();        // S >= 4 always

    int a_row = warp_m * 32 + (lane & 7) + ((lane >> 3) & 1) * 8;
    int a_col = (lane >> 4) * 8;
    int b_row = nb + (lane & 7) + (lane >> 4) * 8;
    int b_col = ((lane >> 3) & 1) * 8;

    int buf = 0;
    for (int s = 0; s < S; s++) {
        CP_WAIT1();
        __syncthreads();

        if (s + 2 < S) {
            int nbuf = buf + 2; if (nbuf >= 3) nbuf -= 3;
            load_stage(s + 2, nbuf);
            CP_COMMIT();
        } else {
            CP_COMMIT();                  // empty group: keeps wait accounting exact
        }

        uint32_t aB = sb + buf * HSTG;
        uint32_t bB = aB + 18432;
#pragma unroll
        for (int h2 = 0; h2 < 4; h2++) {
            int kb = h2 * 16;
            uint32_t af[2][4];
#pragma unroll
            for (int mt = 0; mt < 2; mt++) {
                uint32_t ad = aB + (uint32_t)((a_row + mt * 16) * 72 + a_col + kb) * 2;
                LDSM4(af[mt][0], af[mt][1], af[mt][2], af[mt][3], ad);
            }
            uint32_t bf[8][2];
#pragma unroll
            for (int p = 0; p < 4; p++) {
                uint32_t bd = bB + (uint32_t)((b_row + p * 16) * 72 + b_col + kb) * 2;
                LDSM4(bf[2 * p][0], bf[2 * p][1], bf[2 * p + 1][0], bf[2 * p + 1][1], bd);
            }
#pragma unroll
            for (int nt = 0; nt < 8; nt++) {
                mma_f16(acc[0][nt], af[0], bf[nt][0], bf[nt][1]);
                mma_f16(acc[1][nt], af[1], bf[nt][0], bf[nt][1]);
            }
        }
        if (++buf >= 3) buf -= 3;
    }

    int relu = flags & 1, halfout = flags & 2;
#pragma unroll
    for (int mt = 0; mt < 2; mt++) {
        int r = row0 + warp_m * 32 + mt * 16 + lr;
#pragma unroll
        for (int nt = 0; nt < 8; nt++) {
            int c = col0 + nb + nt * 8 + 2 * lc;
            float2 bsv = *(const float2*)(bias + c);
            float2 o0, o1;
            o0.x = acc[mt][nt][0] + bsv.x; o0.y = acc[mt][nt][1] + bsv.y;
            o1.x = acc[mt][nt][2] + bsv.x; o1.y = acc[mt][nt][3] + bsv.y;
            if (relu) {
                o0.x = fmaxf(o0.x, 0.f); o0.y = fmaxf(o0.y, 0.f);
                o1.x = fmaxf(o1.x, 0.f); o1.y = fmaxf(o1.y, 0.f);
            }
            if (halfout) {
                __half* C = (__half*)Cp;
                *(__half2*)(C + (size_t)r * N + c)       = __floats2half2_rn(o0.x, o0.y);
                *(__half2*)(C + (size_t)(r + 8) * N + c) = __floats2half2_rn(o1.x, o1.y);
            } else {
                float* C = (float*)Cp;
                *(float2*)(C + (size_t)r * N + c)       = o0;
                *(float2*)(C + (size_t)(r + 8) * N + c) = o1;
            }
        }
    }
}

// ---------------------------------------------------------------------------
// 3b) Fused GEMM + residual + LayerNorm (Wo, W2). N = 256 fixed.
//     512 threads, tile 128x256, grid (1, 129). finalize=1: write the padded
//     [B,510,256] output directly (expand fused), skipping g_x/g_xh.
// ---------------------------------------------------------------------------
#define GLSTG 55296                        // A 18432 + B 36864
#define GLN_SMEM (3 * GLSTG)               // 165888

__global__ __launch_bounds__(512, 1) void gemm_ln_kernel(
    const __half* __restrict__ A, const __half* __restrict__ Bt,
    const float* __restrict__ bias, const float* __restrict__ resid,
    const float* __restrict__ lng, const float* __restrict__ lnb,
    float* __restrict__ Xout, __half* __restrict__ Xhout,
    float* __restrict__ Out, int K, int finalize)
{
    extern __shared__ char smc[];
    uint32_t sb = smem_u32(smc);

    int tid = threadIdx.x;
    int wid = tid >> 5, lane = tid & 31;
    int warp_m = wid & 3;
    int warp_n = wid >> 2;                 // 0..3
    int nb = warp_n * 64;
    int row0 = blockIdx.y * 128;
    int lr = lane >> 2, lc = lane & 3;

    float acc[2][8][4];
#pragma unroll
    for (int mt = 0; mt < 2; mt++)
#pragma unroll
        for (int nt = 0; nt < 8; nt++)
#pragma unroll
            for (int i = 0; i < 4; i++) acc[mt][nt][i] = 0.f;

    const int S = K >> 6;

    auto load_stage = [&](int s, int bufi) {
        int k0 = s << 6;
        uint32_t base = sb + bufi * GLSTG;
#pragma unroll
        for (int i = 0; i < 2; i++) {      // A: 128 rows x 8 chunks = 1024
            int e = tid + i * 512;
            int r = e >> 3, c = e & 7;
            CP16(base + (uint32_t)(r * 72 + c * 8) * 2,
                 A + (size_t)(row0 + r) * K + k0 + c * 8);
        }
#pragma unroll
        for (int i = 0; i < 4; i++) {      // B: 256 rows x 8 chunks = 2048
            int e = tid + i * 512;
            int r = e >> 3, c = e & 7;
            CP16(base + 18432 + (uint32_t)(r * 72 + c * 8) * 2,
                 Bt + (size_t)r * K + k0 + c * 8);
        }
    };

    load_stage(0, 0); CP_COMMIT();
    load_stage(1, 1); CP_COMMIT();

    int a_row = warp_m * 32 + (lane & 7) + ((lane >> 3) & 1) * 8;
    int a_col = (lane >> 4) * 8;
    int b_row = nb + (lane & 7) + (lane >> 4) * 8;
    int b_col = ((lane >> 3) & 1) * 8;

    int buf = 0;
    for (int s = 0; s < S; s++) {
        CP_WAIT1();
        __syncthreads();

        if (s + 2 < S) {
            int nbuf = buf + 2; if (nbuf >= 3) nbuf -= 3;
            load_stage(s + 2, nbuf);
            CP_COMMIT();
        } else {
            CP_COMMIT();
        }

        uint32_t aB = sb + buf * GLSTG;
        uint32_t bB = aB + 18432;
#pragma unroll
        for (int h2 = 0; h2 < 4; h2++) {
            int kb = h2 * 16;
            uint32_t af[2][4];
#pragma unroll
            for (int mt = 0; mt < 2; mt++) {
                uint32_t ad = aB + (uint32_t)((a_row + mt * 16) * 72 + a_col + kb) * 2;
                LDSM4(af[mt][0], af[mt][1], af[mt][2], af[mt][3], ad);
            }
            uint32_t bf[8][2];
#pragma unroll
            for (int p = 0; p < 4; p++) {
                uint32_t bd = bB + (uint32_t)((b_row + p * 16) * 72 + b_col + kb) * 2;
                LDSM4(bf[2 * p][0], bf[2 * p][1], bf[2 * p + 1][0], bf[2 * p + 1][1], bd);
            }
#pragma unroll
            for (int nt = 0; nt < 8; nt++) {
                mma_f16(acc[0][nt], af[0], bf[nt][0], bf[nt][1]);
                mma_f16(acc[1][nt], af[1], bf[nt][0], bf[nt][1]);
            }
        }
        if (++buf >= 3) buf -= 3;
    }

    // ---- epilogue: residual + bias, then row LayerNorm across the CTA ----
    __syncthreads();                        // stage buffers now reusable
    float* ssum = (float*)smc;              // [128][4]
    float* ssq  = ssum + 512;               // [128][4]

#pragma unroll
    for (int mt = 0; mt < 2; mt++) {
        int rl0 = warp_m * 32 + mt * 16 + lr;
#pragma unroll
        for (int nt = 0; nt < 8; nt++) {
            int c = nb + nt * 8 + 2 * lc;
            float2 bs = *(const float2*)(bias + c);
            float2 rv0 = *(const float2*)(resid + (size_t)(row0 + rl0) * D_ + c);
            float2 rv1 = *(const float2*)(resid + (size_t)(row0 + rl0 + 8) * D_ + c);
            acc[mt][nt][0] += bs.x + rv0.x;
            acc[mt][nt][1] += bs.y + rv0.y;
            acc[mt][nt][2] += bs.x + rv1.x;
            acc[mt][nt][3] += bs.y + rv1.y;
        }
#pragma unroll
        for (int v = 0; v < 2; v++) {
            float Sm = 0.f, Qm = 0.f;
#pragma unroll
            for (int nt = 0; nt < 8; nt++) {
                float a = acc[mt][nt][2 * v], b = acc[mt][nt][2 * v + 1];
                Sm += a + b;
                Qm += a * a + b * b;
            }
            Sm += __shfl_xor_sync(0xffffffffu, Sm, 1);
            Sm += __shfl_xor_sync(0xffffffffu, Sm, 2);
            Qm += __shfl_xor_sync(0xffffffffu, Qm, 1);
            Qm += __shfl_xor_sync(0xffffffffu, Qm, 2);
            if (lc == 0) {
                ssum[(rl0 + v * 8) * 4 + warp_n] = Sm;
                ssq [(rl0 + v * 8) * 4 + warp_n] = Qm;
            }
        }
    }
    __syncthreads();

#pragma unroll
    for (int mt = 0; mt < 2; mt++) {
#pragma unroll
        for (int v = 0; v < 2; v++) {
            int rl = warp_m * 32 + mt * 16 + v * 8 + lr;
            float Sm = ssum[rl * 4 + 0] + ssum[rl * 4 + 1] +
                       ssum[rl * 4 + 2] + ssum[rl * 4 + 3];
            float Qm = ssq[rl * 4 + 0] + ssq[rl * 4 + 1] +
                       ssq[rl * 4 + 2] + ssq[rl * 4 + 3];
            float mean = Sm * (1.f / 256.f);
            float var  = Qm * (1.f / 256.f) - mean * mean;
            float rs = rsqrtf(var + 1e-5f);

            float2 vals[8];
#pragma unroll
            for (int nt = 0; nt < 8; nt++) {
                int c = nb + nt * 8 + 2 * lc;
                float2 gv = *(const float2*)(lng + c);
                float2 bv = *(const float2*)(lnb + c);
                vals[nt].x = gv.x * (acc[mt][nt][2 * v]     - mean) * rs + bv.x;
                vals[nt].y = gv.y * (acc[mt][nt][2 * v + 1] - mean) * rs + bv.y;
            }

            if (!finalize) {
                size_t rowoff = (size_t)(row0 + rl) * D_;
#pragma unroll
                for (int nt = 0; nt < 8; nt++) {
                    int c = nb + nt * 8 + 2 * lc;
                    *(float2*)(Xout + rowoff + c) = vals[nt];
                    *(__half2*)(Xhout + rowoff + c) = __floats2half2_rn(vals[nt].x, vals[nt].y);
                }
            } else {
                int grow = row0 + rl;
                int pb = grow / R_;
                int rr = grow - pb * R_;
                if (rr < V_) {
                    size_t base = ((size_t)(pb * SEQ + PADV + rr)) * D_;
#pragma unroll
                    for (int nt = 0; nt < 8; nt++) {
                        int c = nb + nt * 8 + 2 * lc;
                        *(float2*)(Out + base + c) = vals[nt];
                    }
                } else {
                    for (int pos = 0; pos < PADV; pos++) {
                        size_t base = ((size_t)(pb * SEQ + pos)) * D_;
#pragma unroll
                        for (int nt = 0; nt < 8; nt++) {
                            int c = nb + nt * 8 + 2 * lc;
                            *(float2*)(Out + base + c) = vals[nt];
                        }
                    }
                }
            }
        }
    }
}

// ---------------------------------------------------------------------------
// 4) fp16 ldmatrix attention (unchanged from R10)
// ---------------------------------------------------------------------------
#define HST 136
#define AVH (128 * HST)
#define AQH (2 * 128 * HST)
#define AFB (3 * 128 * HST * 2)
#define ATTN_SMEM (AFB + 5 * 128 * 4)

__global__ __launch_bounds__(256) void attn_kernel(
    const __half* __restrict__ qkv, __half* __restrict__ ctx)
{
    extern __shared__ char asmem[];
    __half* Kh = (__half*)asmem;
    __half* Vh = Kh + AVH;
    __half* Qh = Kh + AQH;
    float* vpad = (float*)(asmem + AFB);
    float* kpad = vpad + 128;
    float* qpad = kpad + 128;
    float* spad = qpad + 128;
    float* wpq  = spad + 128;
    uint32_t sbk = smem_u32(Kh);
    uint32_t sbv = smem_u32(Vh);
    uint32_t sbq = smem_u32(Qh);

    const float scale = 0.08838834764831845f;

    int tid = threadIdx.x;
    int bh = blockIdx.x;
    int b = bh >> 1, h = bh & 1;
    size_t rb = (size_t)(b * R_) * 768;
    int qoff = h * DH, koff = 256 + h * DH, voff = 512 + h * DH;

    for (int e = tid; e < 128 * 16; e += 256) {
        int r = e >> 4, c = (e & 15) << 3;
        const __half* src = qkv + rb + (size_t)r * 768;
        *(uint4*)(Kh + r * HST + c) = *(const uint4*)(src + koff + c);
        *(uint4*)(Qh + r * HST + c) = *(const uint4*)(src + qoff + c);
        *(uint4*)(Vh + r * HST + c) = *(const uint4*)(src + voff + c);
    }
    if (tid < 128) {
        const __half* src = qkv + rb + (size_t)128 * 768;
        kpad[tid] = __half2float(src[koff + tid]);
        vpad[tid] = __half2float(src[voff + tid]);
        qpad[tid] = __half2float(src[qoff + tid]);
    }
    __syncthreads();

    {   // spad[i] = scale * dot(Q_i, kpad)
        int row = tid >> 1, hf = tid & 1;
        const __half* qp = Qh + row * HST + hf * 64;
        const float* kp = kpad + hf * 64;
        float a = 0.f;
#pragma unroll 16
        for (int d = 0; d < 64; d++) a += __half2float(qp[d]) * kp[d];
        a += __shfl_xor_sync(0xffffffffu, a, 1);
        if (hf == 0) spad[row] = a * scale;
    }
    __syncthreads();

    int wid = tid >> 5, lane = tid & 31;
    int lr = lane >> 2, lc = lane & 3;
    int m0 = wid * 16;
    int r0 = m0 + lr, r1 = m0 + 8 + lr;

    int a_row = m0 + (lane & 15);
    int a_col = (lane >> 4) * 8;
    int b_row = (lane & 7) + (lane >> 4) * 8;
    int b_col = ((lane >> 3) & 1) * 8;
    int vb_row = (lane & 7) + ((lane >> 3) & 1) * 8;
    int vb_col = (lane >> 4) * 8;

    float acc[16][4];
#pragma unroll
    for (int nt = 0; nt < 16; nt++)
#pragma unroll
        for (int i = 0; i < 4; i++) acc[nt][i] = 0.f;

    // phase 1: S = Q @ K^T
#pragma unroll
    for (int ks = 0; ks < 8; ks++) {
        int kb = ks * 16;
        uint32_t af[4];
        LDSM4(af[0], af[1], af[2], af[3],
              sbq + (uint32_t)(a_row * HST + a_col + kb) * 2);
#pragma unroll
        for (int p = 0; p < 8; p++) {
            uint32_t b0, b1, b2, b3;
            LDSM4(b0, b1, b2, b3,
                  sbk + (uint32_t)((p * 16 + b_row) * HST + b_col + kb) * 2);
            mma_f16(acc[2 * p],     af, b0, b1);
            mma_f16(acc[2 * p + 1], af, b2, b3);
        }
    }

    float sp0 = spad[r0], sp1 = spad[r1];
    float mx0 = sp0, mx1 = sp1;
#pragma unroll
    for (int nt = 0; nt < 16; nt++) {
        acc[nt][0] *= scale; acc[nt][1] *= scale;
        acc[nt][2] *= scale; acc[nt][3] *= scale;
        mx0 = fmaxf(mx0, fmaxf(acc[nt][0], acc[nt][1]));
        mx1 = fmaxf(mx1, fmaxf(acc[nt][2], acc[nt][3]));
    }
    mx0 = fmaxf(mx0, __shfl_xor_sync(0xffffffffu, mx0, 1));
    mx0 = fmaxf(mx0, __shfl_xor_sync(0xffffffffu, mx0, 2));
    mx1 = fmaxf(mx1, __shfl_xor_sync(0xffffffffu, mx1, 1));
    mx1 = fmaxf(mx1, __shfl_xor_sync(0xffffffffu, mx1, 2));

    float s0 = 0.f, s1 = 0.f;
#pragma unroll
    for (int nt = 0; nt < 16; nt++) {
        acc[nt][0] = expf(acc[nt][0] - mx0); s0 += acc[nt][0];
        acc[nt][1] = expf(acc[nt][1] - mx0); s0 += acc[nt][1];
        acc[nt][2] = expf(acc[nt][2] - mx1); s1 += acc[nt][2];
        acc[nt][3] = expf(acc[nt][3] - mx1); s1 += acc[nt][3];
    }
    s0 += __shfl_xor_sync(0xffffffffu, s0, 1);
    s0 += __shfl_xor_sync(0xffffffffu, s0, 2);
    s1 += __shfl_xor_sync(0xffffffffu, s1, 1);
    s1 += __shfl_xor_sync(0xffffffffu, s1, 2);

    float ep0 = 382.f * expf(sp0 - mx0);
    float ep1 = 382.f * expf(sp1 - mx1);
    float inv0 = 1.f / (s0 + ep0);
    float inv1 = 1.f / (s1 + ep1);
    float wpad0 = ep0 * inv0, wpad1 = ep1 * inv1;

#pragma unroll
    for (int nt = 0; nt < 16; nt++) {
        int c = nt * 8 + 2 * lc;
        *(__half2*)(Qh + r0 * HST + c) =
            __floats2half2_rn(acc[nt][0] * inv0, acc[nt][1] * inv0);
        *(__half2*)(Qh + r1 * HST + c) =
            __floats2half2_rn(acc[nt][2] * inv1, acc[nt][3] * inv1);
    }
    __syncwarp();

    // phase 2: O = P @ V (B from row-major Vh via ldmatrix.trans)
#pragma unroll
    for (int nt = 0; nt < 16; nt++)
#pragma unroll
        for (int i = 0; i < 4; i++) acc[nt][i] = 0.f;

#pragma unroll
    for (int ks = 0; ks < 8; ks++) {
        uint32_t af[4];
        LDSM4(af[0], af[1], af[2], af[3],
              sbq + (uint32_t)(a_row * HST + a_col + ks * 16) * 2);
#pragma unroll
        for (int p = 0; p < 8; p++) {
            uint32_t b0, b1, b2, b3;
            LDSM4T(b0, b1, b2, b3,
                   sbv + (uint32_t)((ks * 16 + vb_row) * HST + p * 16 + vb_col) * 2);
            mma_f16(acc[2 * p],     af, b0, b1);
            mma_f16(acc[2 * p + 1], af, b2, b3);
        }
    }

    size_t cb = (size_t)(b * R_) * D_ + h * DH;
#pragma unroll
    for (int nt = 0; nt < 16; nt++) {
        int c = nt * 8 + 2 * lc;
        *(__half2*)(ctx + cb + (size_t)r0 * D_ + c) =
            __floats2half2_rn(acc[nt][0] + wpad0 * vpad[c],
                              acc[nt][1] + wpad0 * vpad[c + 1]);
        *(__half2*)(ctx + cb + (size_t)r1 * D_ + c) =
            __floats2half2_rn(acc[nt][2] + wpad1 * vpad[c],
                              acc[nt][3] + wpad1 * vpad[c + 1]);
    }

    // pad query (row 128): scalar path on warp 0
    if (wid == 0) {
        float s[4];
#pragma unroll
        for (int i = 0; i < 4; i++) {
            int j = lane + 32 * i;
            const __half* kr = Kh + j * HST;
            float a = 0.f;
#pragma unroll 16
            for (int d = 0; d < 128; d++) a += qpad[d] * __half2float(kr[d]);
            s[i] = a * scale;
        }
        float spp = 0.f;
#pragma unroll 16
        for (int d = 0; d < 128; d++) spp += qpad[d] * kpad[d];
        spp *= scale;

        float m = fmaxf(fmaxf(s[0], s[1]), fmaxf(s[2], s[3]));
#pragma unroll
        for (int o = 16; o > 0; o >>= 1) m = fmaxf(m, __shfl_xor_sync(0xffffffffu, m, o));
        m = fmaxf(m, spp);
        float su = 0.f;
#pragma unroll
        for (int i = 0; i < 4; i++) { s[i] = expf(s[i] - m); su += s[i]; }
#pragma unroll
        for (int o = 16; o > 0; o >>= 1) su += __shfl_xor_sync(0xffffffffu, su, o);
        float ep = 382.f * expf(spp - m);
        float inv = 1.f / (su + ep);
        float wp = ep * inv;
#pragma unroll
        for (int i = 0; i < 4; i++) wpq[lane + 32 * i] = s[i] * inv;
        __syncwarp();

        float o[4];
#pragma unroll
        for (int i = 0; i < 4; i++) o[i] = wp * vpad[lane + 32 * i];
        for (int j = 0; j < 128; j++) {
            float wj = wpq[j];
            const __half* vr = Vh + j * HST;
#pragma unroll
            for (int i = 0; i < 4; i++)
                o[i] += wj * __half2float(vr[lane + 32 * i]);
        }
#pragma unroll
        for (int i = 0; i < 4; i++)
            ctx[cb + (size_t)128 * D_ + lane + 32 * i] = __float2half(o[i]);
    }
}

// ---------------------------------------------------------------------------
extern "C" void kernel_launch(void* const* d_in, const int* in_sizes, int n_in,
                              void* d_out, int out_size)
{
    const int*   codes   = (const int*)  d_in[0];
    const float* times   = (const float*)d_in[3];
    const float* cemb    = (const float*)d_in[4];
    const float* pad_emb = (const float*)d_in[5];
    const float* Wq = (const float*)d_in[6];
    const float* Wk = (const float*)d_in[7];
    const float* Wv = (const float*)d_in[8];
    const float* Wo = (const float*)d_in[9];
    const float* bq = (const float*)d_in[10];
    const float* bk = (const float*)d_in[11];
    const float* bv = (const float*)d_in[12];
    const float* bo = (const float*)d_in[13];
    const float* ln1g = (const float*)d_in[14];
    const float* ln1b = (const float*)d_in[15];
    const float* W1 = (const float*)d_in[16];
    const float* b1 = (const float*)d_in[17];
    const float* W2 = (const float*)d_in[18];
    const float* b2 = (const float*)d_in[19];
    const float* ln2g = (const float*)d_in[20];
    const float* ln2b = (const float*)d_in[21];
    float* out = (float*)d_out;
    (void)in_sizes; (void)n_in; (void)out_size;

    cudaFuncSetAttribute(attn_kernel, cudaFuncAttributeMaxDynamicSharedMemorySize,
                         ATTN_SMEM);
    cudaFuncSetAttribute(hgemm_kernel, cudaFuncAttributeMaxDynamicSharedMemorySize,
                         HGEMM_SMEM);
    cudaFuncSetAttribute(gemm_ln_kernel, cudaFuncAttributeMaxDynamicSharedMemorySize,
                         GLN_SMEM);

    void* p;
    cudaGetSymbolAddress(&p, g_x);     float*  x     = (float*)p;
    cudaGetSymbolAddress(&p, g_qkvh);  __half* qkvh  = (__half*)p;
    cudaGetSymbolAddress(&p, g_xh);    __half* xh    = (__half*)p;
    cudaGetSymbolAddress(&p, g_ctxh);  __half* ctxh  = (__half*)p;
    cudaGetSymbolAddress(&p, g_h1h);   __half* h1h   = (__half*)p;
    cudaGetSymbolAddress(&p, g_wqkvh); __half* wqkvh = (__half*)p;
    cudaGetSymbolAddress(&p, g_woh);   __half* woh   = (__half*)p;
    cudaGetSymbolAddress(&p, g_w1h);   __half* w1h   = (__half*)p;
    cudaGetSymbolAddress(&p, g_w2h);   __half* w2h   = (__half*)p;
    cudaGetSymbolAddress(&p, g_bqkv);  float*  bqkv  = (float*)p;

    pack_all_kernel<<<dim3(32, 8, 12), dim3(32, 8)>>>(Wq, Wk, Wv, Wo, W1, W2);
    pack_bqkv_kernel<<<NL * 768 / 256, 256>>>(bq, bk, bv);
    embed_kernel<<<B_ * V_ + B_, 256>>>(codes, times, cemb, pad_emb);

    dim3 g768 (6, MROWS / 128);
    dim3 gLN  (1, MROWS / 128);
    dim3 g1024(8, MROWS / 128);

    for (int l = 0; l < NL; l++) {
        hgemm_kernel<<<g768, 256, HGEMM_SMEM>>>(
            xh, wqkvh + (size_t)l * 768 * 256, bqkv + l * 768, qkvh,
            MROWS, 768, D_, 2);

        attn_kernel<<<B_ * 2, 256, ATTN_SMEM>>>(qkvh, ctxh);

        gemm_ln_kernel<<<gLN, 512, GLN_SMEM>>>(
            ctxh, woh + (size_t)l * 65536, bo + l * D_,
            x, ln1g + l * D_, ln1b + l * D_, x, xh, out, D_, 0);

        hgemm_kernel<<<g1024, 256, HGEMM_SMEM>>>(
            xh, w1h + (size_t)l * 262144, b1 + l * DFF, h1h,
            MROWS, DFF, D_, 3);

        gemm_ln_kernel<<<gLN, 512, GLN_SMEM>>>(
            h1h, w2h + (size_t)l * 262144, b2 + l * D_,
            x, ln2g + l * D_, ln2b + l * D_, x, xh, out, DFF,
            (l == NL - 1) ? 1 : 0);
    }
}

// round 17
// speedup vs baseline: 1.0532x; 1.0532x over previous
#include <cuda_runtime.h>
#include <cuda_fp16.h>
#include <math.h>
#include <stdint.h>

// ---------------------------------------------------------------------------
// VisitTransformer on GB300 — compact rows, fp16 mma.sync GEMMs (64x64 warp
// tiles, 64-wide K-stages) + fp16 ldmatrix attention; LN fused into Wo/W2
// epilogues; output expansion fused into the final W2 epilogue.
// Compact: 129 rows/person (128 real + 1 pad row; pad key multiplicity 382).
// ---------------------------------------------------------------------------

#define B_    128
#define V_    128
#define CPV   16
#define SEQ   510
#define PADV  382
#define D_    256
#define DH    128
#define DFF   1024
#define R_    129
#define MROWS (B_ * R_)    // 16512
#define NL    2

// scratch (device globals; allocation-free rule)
__device__ float  g_x   [MROWS * D_];
__device__ __align__(16) __half g_qkvh[MROWS * 768];
__device__ __align__(16) __half g_xh  [MROWS * D_];
__device__ __align__(16) __half g_ctxh[MROWS * D_];
__device__ __align__(16) __half g_h1h [MROWS * DFF];
__device__ __align__(16) __half g_wqkvh[NL * 768 * 256];   // [n][k]
__device__ __align__(16) __half g_woh  [NL * 256 * 256];   // [n][k]
__device__ __align__(16) __half g_w1h  [NL * 1024 * 256];  // [n][k]
__device__ __align__(16) __half g_w2h  [NL * 256 * 1024];  // [n][k]
__device__ float  g_bqkv[NL * 768];

// ---------------------------------------------------------------------------
// helpers
// ---------------------------------------------------------------------------
__device__ __forceinline__ uint32_t smem_u32(const void* p) {
    uint32_t r;
    asm("{ .reg .u64 t; cvta.to.shared.u64 t, %1; cvt.u32.u64 %0, t; }"
        : "=r"(r) : "l"(p));
    return r;
}
#define CP16(dst, src) \
    asm volatile("cp.async.cg.shared.global [%0], [%1], 16;" \
                 :: "r"(dst), "l"(src) : "memory")
#define CP_COMMIT() asm volatile("cp.async.commit_group;" ::: "memory")
#define CP_WAIT1()  asm volatile("cp.async.wait_group 1;" ::: "memory")

#define LDSM4(r0, r1, r2, r3, addr) \
    asm volatile("ldmatrix.sync.aligned.m8n8.x4.shared.b16 {%0,%1,%2,%3}, [%4];" \
                 : "=r"(r0), "=r"(r1), "=r"(r2), "=r"(r3) : "r"(addr))
#define LDSM4T(r0, r1, r2, r3, addr) \
    asm volatile("ldmatrix.sync.aligned.m8n8.x4.trans.shared.b16 {%0,%1,%2,%3}, [%4];" \
                 : "=r"(r0), "=r"(r1), "=r"(r2), "=r"(r3) : "r"(addr))

__device__ __forceinline__ void mma_f16(float* c, const uint32_t* a,
                                        uint32_t b0, uint32_t b1) {
    asm volatile(
        "mma.sync.aligned.m16n8k16.row.col.f32.f16.f16.f32 "
        "{%0,%1,%2,%3}, {%4,%5,%6,%7}, {%8,%9}, {%0,%1,%2,%3};"
        : "+f"(c[0]), "+f"(c[1]), "+f"(c[2]), "+f"(c[3])
        : "r"(a[0]), "r"(a[1]), "r"(a[2]), "r"(a[3]), "r"(b0), "r"(b1));
}

// ---------------------------------------------------------------------------
// 1) Embedding + pad rows (merged)
// ---------------------------------------------------------------------------
__global__ __launch_bounds__(256) void embed_kernel(
    const int* __restrict__ codes, const float* __restrict__ times,
    const float* __restrict__ emb, const float* __restrict__ pad_emb)
{
    int d = threadIdx.x;
    if (blockIdx.x >= B_ * V_) {
        int b = blockIdx.x - B_ * V_;
        float r = pad_emb[d];
        size_t off = (size_t)(b * R_ + V_) * D_ + d;
        g_x[off]  = r;
        g_xh[off] = __float2half(r);
        return;
    }
    int t = blockIdx.x;
    int b = t >> 7, vv = t & 127;

    float acc = 0.f;
    const int* cp = codes + t * CPV;
#pragma unroll
    for (int c = 0; c < CPV; c++) {
        int code = __ldg(cp + c);
        acc += __ldg(emb + (size_t)code * D_ + d);
    }
    float tm = fminf(fmaxf(__ldg(times + t), 0.f), 364.f);
    int j = d & 127;
    float ts  = exp2f(-0.051905126482615036f * (float)j);
    float ang = tm * ts;
    float te  = (d < 128) ? sinf(ang) : cosf(ang);
    float r = acc + te;
    size_t off = (size_t)(b * R_ + vv) * D_ + d;
    g_x[off]  = r;
    g_xh[off] = __float2half(r);
}

// ---------------------------------------------------------------------------
// 2) Weight packing: transpose + convert to fp16 [N][K]. grid.z = job.
// ---------------------------------------------------------------------------
__global__ void pack_all_kernel(
    const float* __restrict__ Wq, const float* __restrict__ Wk,
    const float* __restrict__ Wv, const float* __restrict__ Wo,
    const float* __restrict__ W1, const float* __restrict__ W2)
{
    __shared__ float t[32][33];
    int job = blockIdx.z;
    int l = job & 1, w = job >> 1;
    const float* src; __half* dst; int K, N;
    switch (w) {
        case 0:  src = Wq + (size_t)l * 65536;  dst = g_wqkvh + ((size_t)l * 768 + 0)   * 256; K = 256;  N = 256;  break;
        case 1:  src = Wk + (size_t)l * 65536;  dst = g_wqkvh + ((size_t)l * 768 + 256) * 256; K = 256;  N = 256;  break;
        case 2:  src = Wv + (size_t)l * 65536;  dst = g_wqkvh + ((size_t)l * 768 + 512) * 256; K = 256;  N = 256;  break;
        case 3:  src = Wo + (size_t)l * 65536;  dst = g_woh  + (size_t)l * 65536;  K = 256;  N = 256;  break;
        case 4:  src = W1 + (size_t)l * 262144; dst = g_w1h  + (size_t)l * 262144; K = 256;  N = 1024; break;
        default: src = W2 + (size_t)l * 262144; dst = g_w2h  + (size_t)l * 262144; K = 1024; N = 256;  break;
    }
    int n0, k0;
    if (w == 5) { k0 = blockIdx.x * 32; n0 = blockIdx.y * 32; }
    else        { n0 = blockIdx.x * 32; k0 = blockIdx.y * 32; }
    if (n0 >= N || k0 >= K) return;
    int x = threadIdx.x, y = threadIdx.y;
#pragma unroll
    for (int i = 0; i < 32; i += 8)
        t[y + i][x] = src[(size_t)(k0 + y + i) * N + n0 + x];
    __syncthreads();
#pragma unroll
    for (int i = 0; i < 32; i += 8)
        dst[(size_t)(n0 + y + i) * K + k0 + x] = __float2half(t[x][y + i]);
}

__global__ void pack_bqkv_kernel(
    const float* __restrict__ bq, const float* __restrict__ bk,
    const float* __restrict__ bv)
{
    int idx = blockIdx.x * 256 + threadIdx.x;
    int l = idx / 768, n = idx - l * 768;
    int sel = n >> 8, nn = n & 255;
    const float* bb = (sel == 0) ? bq : (sel == 1) ? bk : bv;
    g_bqkv[idx] = bb[l * 256 + nn];
}

// ---------------------------------------------------------------------------
// 3) fp16 mma.sync GEMM (QKV, W1): C[M,N] = A@Bt^T + bias.
//    Block 128x128, 4 warps (2Mx2N), warp tile 64x64, K-stage 64 halves,
//    3-stage cp.async, row stride 72 halves (conflict-free LDSM).
//    flags: bit0 relu, bit1 fp16 output.
// ---------------------------------------------------------------------------
#define HSTG 36864                        // A 18432 + B 18432 per stage
#define HGEMM_SMEM (3 * HSTG)             // 110592

__global__ __launch_bounds__(128, 2) void hgemm_kernel(
    const __half* __restrict__ A, const __half* __restrict__ Bt,
    const float* __restrict__ bias, void* __restrict__ Cp,
    int M, int N, int K, int flags)
{
    extern __shared__ char smc[];
    uint32_t sb = smem_u32(smc);

    int tid = threadIdx.x;
    int wid = tid >> 5, lane = tid & 31;
    int warp_m = wid & 1;                 // 2 x 64 rows
    int warp_n = wid >> 1;                // 2 x 64 cols
    int row0 = blockIdx.y * 128;
    int col0 = blockIdx.x * 128;
    int lr = lane >> 2, lc = lane & 3;

    float acc[4][8][4];
#pragma unroll
    for (int mt = 0; mt < 4; mt++)
#pragma unroll
        for (int nt = 0; nt < 8; nt++)
#pragma unroll
            for (int i = 0; i < 4; i++) acc[mt][nt][i] = 0.f;

    const int S = K >> 6;                 // 64-wide K stages (K >= 256)

    auto load_stage = [&](int s, int bufi) {
        int k0 = s << 6;
        uint32_t base = sb + bufi * HSTG;
#pragma unroll
        for (int i = 0; i < 8; i++) {
            int e = tid + i * 128;        // 0..1023
            int r = e >> 3, c = e & 7;
            CP16(base + (uint32_t)(r * 72 + c * 8) * 2,
                 A + (size_t)(row0 + r) * K + k0 + c * 8);
        }
#pragma unroll
        for (int i = 0; i < 8; i++) {
            int e = tid + i * 128;
            int r = e >> 3, c = e & 7;
            CP16(base + 18432 + (uint32_t)(r * 72 + c * 8) * 2,
                 Bt + (size_t)(col0 + r) * K + k0 + c * 8);
        }
    };

    load_stage(0, 0); CP_COMMIT();
    load_stage(1, 1); CP_COMMIT();        // S >= 4 always

    int a_row = warp_m * 64 + (lane & 7) + ((lane >> 3) & 1) * 8;
    int a_col = (lane >> 4) * 8;
    int b_row = warp_n * 64 + (lane & 7) + (lane >> 4) * 8;
    int b_col = ((lane >> 3) & 1) * 8;

    int buf = 0;
    for (int s = 0; s < S; s++) {
        CP_WAIT1();
        __syncthreads();

        if (s + 2 < S) {
            int nbuf = buf + 2; if (nbuf >= 3) nbuf -= 3;
            load_stage(s + 2, nbuf);
            CP_COMMIT();
        } else {
            CP_COMMIT();                  // empty group keeps accounting exact
        }

        uint32_t aB = sb + buf * HSTG;
        uint32_t bB = aB + 18432;
#pragma unroll
        for (int h2 = 0; h2 < 4; h2++) {
            int kb = h2 * 16;
            uint32_t af[4][4];
#pragma unroll
            for (int mt = 0; mt < 4; mt++) {
                uint32_t ad = aB + (uint32_t)((a_row + mt * 16) * 72 + a_col + kb) * 2;
                LDSM4(af[mt][0], af[mt][1], af[mt][2], af[mt][3], ad);
            }
            uint32_t bf[8][2];
#pragma unroll
            for (int p = 0; p < 4; p++) {
                uint32_t bd = bB + (uint32_t)((b_row + p * 16) * 72 + b_col + kb) * 2;
                LDSM4(bf[2 * p][0], bf[2 * p][1], bf[2 * p + 1][0], bf[2 * p + 1][1], bd);
            }
#pragma unroll
            for (int mt = 0; mt < 4; mt++)
#pragma unroll
                for (int nt = 0; nt < 8; nt++)
                    mma_f16(acc[mt][nt], af[mt], bf[nt][0], bf[nt][1]);
        }
        if (++buf >= 3) buf -= 3;
    }

    int relu = flags & 1, halfout = flags & 2;
#pragma unroll
    for (int mt = 0; mt < 4; mt++) {
        int r = row0 + warp_m * 64 + mt * 16 + lr;
#pragma unroll
        for (int nt = 0; nt < 8; nt++) {
            int c = col0 + warp_n * 64 + nt * 8 + 2 * lc;
            float2 bsv = *(const float2*)(bias + c);
            float2 o0, o1;
            o0.x = acc[mt][nt][0] + bsv.x; o0.y = acc[mt][nt][1] + bsv.y;
            o1.x = acc[mt][nt][2] + bsv.x; o1.y = acc[mt][nt][3] + bsv.y;
            if (relu) {
                o0.x = fmaxf(o0.x, 0.f); o0.y = fmaxf(o0.y, 0.f);
                o1.x = fmaxf(o1.x, 0.f); o1.y = fmaxf(o1.y, 0.f);
            }
            if (halfout) {
                __half* C = (__half*)Cp;
                *(__half2*)(C + (size_t)r * N + c)       = __floats2half2_rn(o0.x, o0.y);
                *(__half2*)(C + (size_t)(r + 8) * N + c) = __floats2half2_rn(o1.x, o1.y);
            } else {
                float* C = (float*)Cp;
                *(float2*)(C + (size_t)r * N + c)       = o0;
                *(float2*)(C + (size_t)(r + 8) * N + c) = o1;
            }
        }
    }
}

// ---------------------------------------------------------------------------
// 3b) Fused GEMM + residual + LayerNorm (Wo, W2). N = 256 fixed.
//     256 threads, 8 warps (2Mx4N), warp tile 64x64, tile 128x256,
//     grid (1, 129). finalize=1: write padded [B,510,256] output directly.
// ---------------------------------------------------------------------------
#define GLSTG 55296                        // A 18432 + B 36864
#define GLN_SMEM (3 * GLSTG)               // 165888

__global__ __launch_bounds__(256, 1) void gemm_ln_kernel(
    const __half* __restrict__ A, const __half* __restrict__ Bt,
    const float* __restrict__ bias, const float* __restrict__ resid,
    const float* __restrict__ lng, const float* __restrict__ lnb,
    float* __restrict__ Xout, __half* __restrict__ Xhout,
    float* __restrict__ Out, int K, int finalize)
{
    extern __shared__ char smc[];
    uint32_t sb = smem_u32(smc);

    int tid = threadIdx.x;
    int wid = tid >> 5, lane = tid & 31;
    int warp_m = wid & 1;                  // 2 x 64 rows
    int warp_n = wid >> 1;                 // 4 x 64 cols
    int nb = warp_n * 64;
    int row0 = blockIdx.y * 128;
    int lr = lane >> 2, lc = lane & 3;

    float acc[4][8][4];
#pragma unroll
    for (int mt = 0; mt < 4; mt++)
#pragma unroll
        for (int nt = 0; nt < 8; nt++)
#pragma unroll
            for (int i = 0; i < 4; i++) acc[mt][nt][i] = 0.f;

    const int S = K >> 6;

    auto load_stage = [&](int s, int bufi) {
        int k0 = s << 6;
        uint32_t base = sb + bufi * GLSTG;
#pragma unroll
        for (int i = 0; i < 4; i++) {      // A: 128 rows x 8 chunks = 1024
            int e = tid + i * 256;
            int r = e >> 3, c = e & 7;
            CP16(base + (uint32_t)(r * 72 + c * 8) * 2,
                 A + (size_t)(row0 + r) * K + k0 + c * 8);
        }
#pragma unroll
        for (int i = 0; i < 8; i++) {      // B: 256 rows x 8 chunks = 2048
            int e = tid + i * 256;
            int r = e >> 3, c = e & 7;
            CP16(base + 18432 + (uint32_t)(r * 72 + c * 8) * 2,
                 Bt + (size_t)r * K + k0 + c * 8);
        }
    };

    load_stage(0, 0); CP_COMMIT();
    load_stage(1, 1); CP_COMMIT();

    int a_row = warp_m * 64 + (lane & 7) + ((lane >> 3) & 1) * 8;
    int a_col = (lane >> 4) * 8;
    int b_row = nb + (lane & 7) + (lane >> 4) * 8;
    int b_col = ((lane >> 3) & 1) * 8;

    int buf = 0;
    for (int s = 0; s < S; s++) {
        CP_WAIT1();
        __syncthreads();

        if (s + 2 < S) {
            int nbuf = buf + 2; if (nbuf >= 3) nbuf -= 3;
            load_stage(s + 2, nbuf);
            CP_COMMIT();
        } else {
            CP_COMMIT();
        }

        uint32_t aB = sb + buf * GLSTG;
        uint32_t bB = aB + 18432;
#pragma unroll
        for (int h2 = 0; h2 < 4; h2++) {
            int kb = h2 * 16;
            uint32_t af[4][4];
#pragma unroll
            for (int mt = 0; mt < 4; mt++) {
                uint32_t ad = aB + (uint32_t)((a_row + mt * 16) * 72 + a_col + kb) * 2;
                LDSM4(af[mt][0], af[mt][1], af[mt][2], af[mt][3], ad);
            }
            uint32_t bf[8][2];
#pragma unroll
            for (int p = 0; p < 4; p++) {
                uint32_t bd = bB + (uint32_t)((b_row + p * 16) * 72 + b_col + kb) * 2;
                LDSM4(bf[2 * p][0], bf[2 * p][1], bf[2 * p + 1][0], bf[2 * p + 1][1], bd);
            }
#pragma unroll
            for (int mt = 0; mt < 4; mt++)
#pragma unroll
                for (int nt = 0; nt < 8; nt++)
                    mma_f16(acc[mt][nt], af[mt], bf[nt][0], bf[nt][1]);
        }
        if (++buf >= 3) buf -= 3;
    }

    // ---- epilogue: residual + bias, then row LayerNorm across the CTA ----
    __syncthreads();                        // stage buffers now reusable
    float* ssum = (float*)smc;              // [128][4]
    float* ssq  = ssum + 512;               // [128][4]

#pragma unroll
    for (int mt = 0; mt < 4; mt++) {
        int rl0 = warp_m * 64 + mt * 16 + lr;
#pragma unroll
        for (int nt = 0; nt < 8; nt++) {
            int c = nb + nt * 8 + 2 * lc;
            float2 bs = *(const float2*)(bias + c);
            float2 rv0 = *(const float2*)(resid + (size_t)(row0 + rl0) * D_ + c);
            float2 rv1 = *(const float2*)(resid + (size_t)(row0 + rl0 + 8) * D_ + c);
            acc[mt][nt][0] += bs.x + rv0.x;
            acc[mt][nt][1] += bs.y + rv0.y;
            acc[mt][nt][2] += bs.x + rv1.x;
            acc[mt][nt][3] += bs.y + rv1.y;
        }
#pragma unroll
        for (int v = 0; v < 2; v++) {
            float Sm = 0.f, Qm = 0.f;
#pragma unroll
            for (int nt = 0; nt < 8; nt++) {
                float a = acc[mt][nt][2 * v], b = acc[mt][nt][2 * v + 1];
                Sm += a + b;
                Qm += a * a + b * b;
            }
            Sm += __shfl_xor_sync(0xffffffffu, Sm, 1);
            Sm += __shfl_xor_sync(0xffffffffu, Sm, 2);
            Qm += __shfl_xor_sync(0xffffffffu, Qm, 1);
            Qm += __shfl_xor_sync(0xffffffffu, Qm, 2);
            if (lc == 0) {
                ssum[(rl0 + v * 8) * 4 + warp_n] = Sm;
                ssq [(rl0 + v * 8) * 4 + warp_n] = Qm;
            }
        }
    }
    __syncthreads();

#pragma unroll
    for (int mt = 0; mt < 4; mt++) {
#pragma unroll
        for (int v = 0; v < 2; v++) {
            int rl = warp_m * 64 + mt * 16 + v * 8 + lr;
            float Sm = ssum[rl * 4 + 0] + ssum[rl * 4 + 1] +
                       ssum[rl * 4 + 2] + ssum[rl * 4 + 3];
            float Qm = ssq[rl * 4 + 0] + ssq[rl * 4 + 1] +
                       ssq[rl * 4 + 2] + ssq[rl * 4 + 3];
            float mean = Sm * (1.f / 256.f);
            float var  = Qm * (1.f / 256.f) - mean * mean;
            float rs = rsqrtf(var + 1e-5f);

            float2 vals[8];
#pragma unroll
            for (int nt = 0; nt < 8; nt++) {
                int c = nb + nt * 8 + 2 * lc;
                float2 gv = *(const float2*)(lng + c);
                float2 bv = *(const float2*)(lnb + c);
                vals[nt].x = gv.x * (acc[mt][nt][2 * v]     - mean) * rs + bv.x;
                vals[nt].y = gv.y * (acc[mt][nt][2 * v + 1] - mean) * rs + bv.y;
            }

            if (!finalize) {
                size_t rowoff = (size_t)(row0 + rl) * D_;
#pragma unroll
                for (int nt = 0; nt < 8; nt++) {
                    int c = nb + nt * 8 + 2 * lc;
                    *(float2*)(Xout + rowoff + c) = vals[nt];
                    *(__half2*)(Xhout + rowoff + c) = __floats2half2_rn(vals[nt].x, vals[nt].y);
                }
            } else {
                int grow = row0 + rl;
                int pb = grow / R_;
                int rr = grow - pb * R_;
                if (rr < V_) {
                    size_t base = ((size_t)(pb * SEQ + PADV + rr)) * D_;
#pragma unroll
                    for (int nt = 0; nt < 8; nt++) {
                        int c = nb + nt * 8 + 2 * lc;
                        *(float2*)(Out + base + c) = vals[nt];
                    }
                } else {
                    for (int pos = 0; pos < PADV; pos++) {
                        size_t base = ((size_t)(pb * SEQ + pos)) * D_;
#pragma unroll
                        for (int nt = 0; nt < 8; nt++) {
                            int c = nb + nt * 8 + 2 * lc;
                            *(float2*)(Out + base + c) = vals[nt];
                        }
                    }
                }
            }
        }
    }
}

// ---------------------------------------------------------------------------
// 4) fp16 ldmatrix attention (unchanged)
// ---------------------------------------------------------------------------
#define HST 136
#define AVH (128 * HST)
#define AQH (2 * 128 * HST)
#define AFB (3 * 128 * HST * 2)
#define ATTN_SMEM (AFB + 5 * 128 * 4)

__global__ __launch_bounds__(256) void attn_kernel(
    const __half* __restrict__ qkv, __half* __restrict__ ctx)
{
    extern __shared__ char asmem[];
    __half* Kh = (__half*)asmem;
    __half* Vh = Kh + AVH;
    __half* Qh = Kh + AQH;
    float* vpad = (float*)(asmem + AFB);
    float* kpad = vpad + 128;
    float* qpad = kpad + 128;
    float* spad = qpad + 128;
    float* wpq  = spad + 128;
    uint32_t sbk = smem_u32(Kh);
    uint32_t sbv = smem_u32(Vh);
    uint32_t sbq = smem_u32(Qh);

    const float scale = 0.08838834764831845f;

    int tid = threadIdx.x;
    int bh = blockIdx.x;
    int b = bh >> 1, h = bh & 1;
    size_t rb = (size_t)(b * R_) * 768;
    int qoff = h * DH, koff = 256 + h * DH, voff = 512 + h * DH;

    for (int e = tid; e < 128 * 16; e += 256) {
        int r = e >> 4, c = (e & 15) << 3;
        const __half* src = qkv + rb + (size_t)r * 768;
        *(uint4*)(Kh + r * HST + c) = *(const uint4*)(src + koff + c);
        *(uint4*)(Qh + r * HST + c) = *(const uint4*)(src + qoff + c);
        *(uint4*)(Vh + r * HST + c) = *(const uint4*)(src + voff + c);
    }
    if (tid < 128) {
        const __half* src = qkv + rb + (size_t)128 * 768;
        kpad[tid] = __half2float(src[koff + tid]);
        vpad[tid] = __half2float(src[voff + tid]);
        qpad[tid] = __half2float(src[qoff + tid]);
    }
    __syncthreads();

    {   // spad[i] = scale * dot(Q_i, kpad)
        int row = tid >> 1, hf = tid & 1;
        const __half* qp = Qh + row * HST + hf * 64;
        const float* kp = kpad + hf * 64;
        float a = 0.f;
#pragma unroll 16
        for (int d = 0; d < 64; d++) a += __half2float(qp[d]) * kp[d];
        a += __shfl_xor_sync(0xffffffffu, a, 1);
        if (hf == 0) spad[row] = a * scale;
    }
    __syncthreads();

    int wid = tid >> 5, lane = tid & 31;
    int lr = lane >> 2, lc = lane & 3;
    int m0 = wid * 16;
    int r0 = m0 + lr, r1 = m0 + 8 + lr;

    int a_row = m0 + (lane & 15);
    int a_col = (lane >> 4) * 8;
    int b_row = (lane & 7) + (lane >> 4) * 8;
    int b_col = ((lane >> 3) & 1) * 8;
    int vb_row = (lane & 7) + ((lane >> 3) & 1) * 8;
    int vb_col = (lane >> 4) * 8;

    float acc[16][4];
#pragma unroll
    for (int nt = 0; nt < 16; nt++)
#pragma unroll
        for (int i = 0; i < 4; i++) acc[nt][i] = 0.f;

    // phase 1: S = Q @ K^T
#pragma unroll
    for (int ks = 0; ks < 8; ks++) {
        int kb = ks * 16;
        uint32_t af[4];
        LDSM4(af[0], af[1], af[2], af[3],
              sbq + (uint32_t)(a_row * HST + a_col + kb) * 2);
#pragma unroll
        for (int p = 0; p < 8; p++) {
            uint32_t b0, b1, b2, b3;
            LDSM4(b0, b1, b2, b3,
                  sbk + (uint32_t)((p * 16 + b_row) * HST + b_col + kb) * 2);
            mma_f16(acc[2 * p],     af, b0, b1);
            mma_f16(acc[2 * p + 1], af, b2, b3);
        }
    }

    float sp0 = spad[r0], sp1 = spad[r1];
    float mx0 = sp0, mx1 = sp1;
#pragma unroll
    for (int nt = 0; nt < 16; nt++) {
        acc[nt][0] *= scale; acc[nt][1] *= scale;
        acc[nt][2] *= scale; acc[nt][3] *= scale;
        mx0 = fmaxf(mx0, fmaxf(acc[nt][0], acc[nt][1]));
        mx1 = fmaxf(mx1, fmaxf(acc[nt][2], acc[nt][3]));
    }
    mx0 = fmaxf(mx0, __shfl_xor_sync(0xffffffffu, mx0, 1));
    mx0 = fmaxf(mx0, __shfl_xor_sync(0xffffffffu, mx0, 2));
    mx1 = fmaxf(mx1, __shfl_xor_sync(0xffffffffu, mx1, 1));
    mx1 = fmaxf(mx1, __shfl_xor_sync(0xffffffffu, mx1, 2));

    float s0 = 0.f, s1 = 0.f;
#pragma unroll
    for (int nt = 0; nt < 16; nt++) {
        acc[nt][0] = expf(acc[nt][0] - mx0); s0 += acc[nt][0];
        acc[nt][1] = expf(acc[nt][1] - mx0); s0 += acc[nt][1];
        acc[nt][2] = expf(acc[nt][2] - mx1); s1 += acc[nt][2];
        acc[nt][3] = expf(acc[nt][3] - mx1); s1 += acc[nt][3];
    }
    s0 += __shfl_xor_sync(0xffffffffu, s0, 1);
    s0 += __shfl_xor_sync(0xffffffffu, s0, 2);
    s1 += __shfl_xor_sync(0xffffffffu, s1, 1);
    s1 += __shfl_xor_sync(0xffffffffu, s1, 2);

    float ep0 = 382.f * expf(sp0 - mx0);
    float ep1 = 382.f * expf(sp1 - mx1);
    float inv0 = 1.f / (s0 + ep0);
    float inv1 = 1.f / (s1 + ep1);
    float wpad0 = ep0 * inv0, wpad1 = ep1 * inv1;

#pragma unroll
    for (int nt = 0; nt < 16; nt++) {
        int c = nt * 8 + 2 * lc;
        *(__half2*)(Qh + r0 * HST + c) =
            __floats2half2_rn(acc[nt][0] * inv0, acc[nt][1] * inv0);
        *(__half2*)(Qh + r1 * HST + c) =
            __floats2half2_rn(acc[nt][2] * inv1, acc[nt][3] * inv1);
    }
    __syncwarp();

    // phase 2: O = P @ V (B from row-major Vh via ldmatrix.trans)
#pragma unroll
    for (int nt = 0; nt < 16; nt++)
#pragma unroll
        for (int i = 0; i < 4; i++) acc[nt][i] = 0.f;

#pragma unroll
    for (int ks = 0; ks < 8; ks++) {
        uint32_t af[4];
        LDSM4(af[0], af[1], af[2], af[3],
              sbq + (uint32_t)(a_row * HST + a_col + ks * 16) * 2);
#pragma unroll
        for (int p = 0; p < 8; p++) {
            uint32_t b0, b1, b2, b3;
            LDSM4T(b0, b1, b2, b3,
                   sbv + (uint32_t)((ks * 16 + vb_row) * HST + p * 16 + vb_col) * 2);
            mma_f16(acc[2 * p],     af, b0, b1);
            mma_f16(acc[2 * p + 1], af, b2, b3);
        }
    }

    size_t cb = (size_t)(b * R_) * D_ + h * DH;
#pragma unroll
    for (int nt = 0; nt < 16; nt++) {
        int c = nt * 8 + 2 * lc;
        *(__half2*)(ctx + cb + (size_t)r0 * D_ + c) =
            __floats2half2_rn(acc[nt][0] + wpad0 * vpad[c],
                              acc[nt][1] + wpad0 * vpad[c + 1]);
        *(__half2*)(ctx + cb + (size_t)r1 * D_ + c) =
            __floats2half2_rn(acc[nt][2] + wpad1 * vpad[c],
                              acc[nt][3] + wpad1 * vpad[c + 1]);
    }

    // pad query (row 128): scalar path on warp 0
    if (wid == 0) {
        float s[4];
#pragma unroll
        for (int i = 0; i < 4; i++) {
            int j = lane + 32 * i;
            const __half* kr = Kh + j * HST;
            float a = 0.f;
#pragma unroll 16
            for (int d = 0; d < 128; d++) a += qpad[d] * __half2float(kr[d]);
            s[i] = a * scale;
        }
        float spp = 0.f;
#pragma unroll 16
        for (int d = 0; d < 128; d++) spp += qpad[d] * kpad[d];
        spp *= scale;

        float m = fmaxf(fmaxf(s[0], s[1]), fmaxf(s[2], s[3]));
#pragma unroll
        for (int o = 16; o > 0; o >>= 1) m = fmaxf(m, __shfl_xor_sync(0xffffffffu, m, o));
        m = fmaxf(m, spp);
        float su = 0.f;
#pragma unroll
        for (int i = 0; i < 4; i++) { s[i] = expf(s[i] - m); su += s[i]; }
#pragma unroll
        for (int o = 16; o > 0; o >>= 1) su += __shfl_xor_sync(0xffffffffu, su, o);
        float ep = 382.f * expf(spp - m);
        float inv = 1.f / (su + ep);
        float wp = ep * inv;
#pragma unroll
        for (int i = 0; i < 4; i++) wpq[lane + 32 * i] = s[i] * inv;
        __syncwarp();

        float o[4];
#pragma unroll
        for (int i = 0; i < 4; i++) o[i] = wp * vpad[lane + 32 * i];
        for (int j = 0; j < 128; j++) {
            float wj = wpq[j];
            const __half* vr = Vh + j * HST;
#pragma unroll
            for (int i = 0; i < 4; i++)
                o[i] += wj * __half2float(vr[lane + 32 * i]);
        }
#pragma unroll
        for (int i = 0; i < 4; i++)
            ctx[cb + (size_t)128 * D_ + lane + 32 * i] = __float2half(o[i]);
    }
}

// ---------------------------------------------------------------------------
extern "C" void kernel_launch(void* const* d_in, const int* in_sizes, int n_in,
                              void* d_out, int out_size)
{
    const int*   codes   = (const int*)  d_in[0];
    const float* times   = (const float*)d_in[3];
    const float* cemb    = (const float*)d_in[4];
    const float* pad_emb = (const float*)d_in[5];
    const float* Wq = (const float*)d_in[6];
    const float* Wk = (const float*)d_in[7];
    const float* Wv = (const float*)d_in[8];
    const float* Wo = (const float*)d_in[9];
    const float* bq = (const float*)d_in[10];
    const float* bk = (const float*)d_in[11];
    const float* bv = (const float*)d_in[12];
    const float* bo = (const float*)d_in[13];
    const float* ln1g = (const float*)d_in[14];
    const float* ln1b = (const float*)d_in[15];
    const float* W1 = (const float*)d_in[16];
    const float* b1 = (const float*)d_in[17];
    const float* W2 = (const float*)d_in[18];
    const float* b2 = (const float*)d_in[19];
    const float* ln2g = (const float*)d_in[20];
    const float* ln2b = (const float*)d_in[21];
    float* out = (float*)d_out;
    (void)in_sizes; (void)n_in; (void)out_size;

    cudaFuncSetAttribute(attn_kernel, cudaFuncAttributeMaxDynamicSharedMemorySize,
                         ATTN_SMEM);
    cudaFuncSetAttribute(hgemm_kernel, cudaFuncAttributeMaxDynamicSharedMemorySize,
                         HGEMM_SMEM);
    cudaFuncSetAttribute(gemm_ln_kernel, cudaFuncAttributeMaxDynamicSharedMemorySize,
                         GLN_SMEM);

    void* p;
    cudaGetSymbolAddress(&p, g_x);     float*  x     = (float*)p;
    cudaGetSymbolAddress(&p, g_qkvh);  __half* qkvh  = (__half*)p;
    cudaGetSymbolAddress(&p, g_xh);    __half* xh    = (__half*)p;
    cudaGetSymbolAddress(&p, g_ctxh);  __half* ctxh  = (__half*)p;
    cudaGetSymbolAddress(&p, g_h1h);   __half* h1h   = (__half*)p;
    cudaGetSymbolAddress(&p, g_wqkvh); __half* wqkvh = (__half*)p;
    cudaGetSymbolAddress(&p, g_woh);   __half* woh   = (__half*)p;
    cudaGetSymbolAddress(&p, g_w1h);   __half* w1h   = (__half*)p;
    cudaGetSymbolAddress(&p, g_w2h);   __half* w2h   = (__half*)p;
    cudaGetSymbolAddress(&p, g_bqkv);  float*  bqkv  = (float*)p;

    pack_all_kernel<<<dim3(32, 8, 12), dim3(32, 8)>>>(Wq, Wk, Wv, Wo, W1, W2);
    pack_bqkv_kernel<<<NL * 768 / 256, 256>>>(bq, bk, bv);
    embed_kernel<<<B_ * V_ + B_, 256>>>(codes, times, cemb, pad_emb);

    dim3 g768 (6, MROWS / 128);
    dim3 gLN  (1, MROWS / 128);
    dim3 g1024(8, MROWS / 128);

    for (int l = 0; l < NL; l++) {
        hgemm_kernel<<<g768, 128, HGEMM_SMEM>>>(
            xh, wqkvh + (size_t)l * 768 * 256, bqkv + l * 768, qkvh,
            MROWS, 768, D_, 2);

        attn_kernel<<<B_ * 2, 256, ATTN_SMEM>>>(qkvh, ctxh);

        gemm_ln_kernel<<<gLN, 256, GLN_SMEM>>>(
            ctxh, woh + (size_t)l * 65536, bo + l * D_,
            x, ln1g + l * D_, ln1b + l * D_, x, xh, out, D_, 0);

        hgemm_kernel<<<g1024, 128, HGEMM_SMEM>>>(
            xh, w1h + (size_t)l * 262144, b1 + l * DFF, h1h,
            MROWS, DFF, D_, 3);

        gemm_ln_kernel<<<gLN, 256, GLN_SMEM>>>(
            h1h, w2h + (size_t)l * 262144, b2 + l * D_,
            x, ln2g + l * D_, ln2b + l * D_, x, xh, out, DFF,
            (l == NL - 1) ? 1 : 0);
    }
}